// round 7
// baseline (speedup 1.0000x reference)
#include <cuda_runtime.h>
#include <cstdint>

#define LUT_MAX 512   // actual LUT is 302 entries

// Final: R1 structure (empirically best across 6 rounds: 45.4us kernel,
// 6.27 TB/s = 79% HBM, roofline for a 3-read/2-write once-touched stream).
// EXACT=true drops the tail bounds check when n4 % blockDim == 0.
template <bool MASK_AS_FLOAT, bool EXACT>
__global__ __launch_bounds__(256)
void octvol_kernel(const int4* __restrict__ labels4,
                   const float4* __restrict__ par4,
                   const float4* __restrict__ tex4,
                   const float* __restrict__ lut,
                   int lut_n,
                   float4* __restrict__ out_vol4,
                   void* __restrict__ out_mask,
                   int n4)
{
    __shared__ float s_lut[LUT_MAX];
    for (int i = threadIdx.x; i < lut_n; i += blockDim.x)
        s_lut[i] = lut[i];
    __syncthreads();

    int idx = blockIdx.x * blockDim.x + threadIdx.x;
    if (!EXACT && idx >= n4) return;

    int4   lb = labels4[idx];
    float4 pa = par4[idx];
    float4 tx = tex4[idx];

    float s0 = s_lut[lb.x];
    float s1 = s_lut[lb.y];
    float s2 = s_lut[lb.z];
    float s3 = s_lut[lb.w];

    float v0 = s0 * tx.x; if (v0 == 0.0f) v0 = 1.0f;
    float v1 = s1 * tx.y; if (v1 == 0.0f) v1 = 1.0f;
    float v2 = s2 * tx.z; if (v2 == 0.0f) v2 = 1.0f;
    float v3 = s3 * tx.w; if (v3 == 0.0f) v3 = 1.0f;

    float4 o;
    o.x = pa.x * v0;
    o.y = pa.y * v1;
    o.z = pa.z * v2;
    o.w = pa.w * v3;
    out_vol4[idx] = o;

    if (MASK_AS_FLOAT) {
        float4 m;
        m.x = lb.x ? 1.0f : 0.0f;
        m.y = lb.y ? 1.0f : 0.0f;
        m.z = lb.z ? 1.0f : 0.0f;
        m.w = lb.w ? 1.0f : 0.0f;
        reinterpret_cast<float4*>(out_mask)[idx] = m;
    } else {
        uchar4 m;
        m.x = lb.x ? 1 : 0;
        m.y = lb.y ? 1 : 0;
        m.z = lb.z ? 1 : 0;
        m.w = lb.w ? 1 : 0;
        reinterpret_cast<uchar4*>(out_mask)[idx] = m;
    }
}

extern "C" void kernel_launch(void* const* d_in, const int* in_sizes, int n_in,
                              void* d_out, int out_size)
{
    // metadata order:
    //   0: vessel_labels  int32  [N]
    //   1: parenchyma     f32    [N]
    //   2: vessel_texture f32    [N]
    //   3: intensity_lut  f32    [302]
    const int*   labels = (const int*)  d_in[0];
    const float* par    = (const float*)d_in[1];
    const float* tex    = (const float*)d_in[2];
    const float* lut    = (const float*)d_in[3];

    int n     = in_sizes[0];
    int lut_n = in_sizes[3];
    int n4    = n / 4;

    float* out_vol = (float*)d_out;

    dim3 block(256);
    dim3 grid((n4 + 255) / 256);
    bool exact = (n4 % 256) == 0;

    if (out_size >= 2 * n) {
        void* out_mask = (void*)(out_vol + n);
        if (exact)
            octvol_kernel<true, true><<<grid, block>>>(
                (const int4*)labels, (const float4*)par, (const float4*)tex,
                lut, lut_n, (float4*)out_vol, out_mask, n4);
        else
            octvol_kernel<true, false><<<grid, block>>>(
                (const int4*)labels, (const float4*)par, (const float4*)tex,
                lut, lut_n, (float4*)out_vol, out_mask, n4);
    } else {
        void* out_mask = (void*)((char*)d_out + (size_t)n * sizeof(float));
        if (exact)
            octvol_kernel<false, true><<<grid, block>>>(
                (const int4*)labels, (const float4*)par, (const float4*)tex,
                lut, lut_n, (float4*)out_vol, out_mask, n4);
        else
            octvol_kernel<false, false><<<grid, block>>>(
                (const int4*)labels, (const float4*)par, (const float4*)tex,
                lut, lut_n, (float4*)out_vol, out_mask, n4);
    }
}

// round 8
// speedup vs baseline: 1.0054x; 1.0054x over previous
#include <cuda_runtime.h>
#include <cstdint>

#define LUT_MAX 512   // actual LUT is 302 entries

// R7 converged structure + __stcs evict-streaming on the two write-once
// output streams (controlled test of the last cache-policy quadrant).
template <bool MASK_AS_FLOAT, bool EXACT>
__global__ __launch_bounds__(256)
void octvol_kernel(const int4* __restrict__ labels4,
                   const float4* __restrict__ par4,
                   const float4* __restrict__ tex4,
                   const float* __restrict__ lut,
                   int lut_n,
                   float4* __restrict__ out_vol4,
                   void* __restrict__ out_mask,
                   int n4)
{
    __shared__ float s_lut[LUT_MAX];
    for (int i = threadIdx.x; i < lut_n; i += blockDim.x)
        s_lut[i] = lut[i];
    __syncthreads();

    int idx = blockIdx.x * blockDim.x + threadIdx.x;
    if (!EXACT && idx >= n4) return;

    int4   lb = labels4[idx];
    float4 pa = par4[idx];
    float4 tx = tex4[idx];

    float s0 = s_lut[lb.x];
    float s1 = s_lut[lb.y];
    float s2 = s_lut[lb.z];
    float s3 = s_lut[lb.w];

    float v0 = s0 * tx.x; if (v0 == 0.0f) v0 = 1.0f;
    float v1 = s1 * tx.y; if (v1 == 0.0f) v1 = 1.0f;
    float v2 = s2 * tx.z; if (v2 == 0.0f) v2 = 1.0f;
    float v3 = s3 * tx.w; if (v3 == 0.0f) v3 = 1.0f;

    float4 o;
    o.x = pa.x * v0;
    o.y = pa.y * v1;
    o.z = pa.z * v2;
    o.w = pa.w * v3;
    __stcs(out_vol4 + idx, o);

    if (MASK_AS_FLOAT) {
        float4 m;
        m.x = lb.x ? 1.0f : 0.0f;
        m.y = lb.y ? 1.0f : 0.0f;
        m.z = lb.z ? 1.0f : 0.0f;
        m.w = lb.w ? 1.0f : 0.0f;
        __stcs(reinterpret_cast<float4*>(out_mask) + idx, m);
    } else {
        uchar4 m;
        m.x = lb.x ? 1 : 0;
        m.y = lb.y ? 1 : 0;
        m.z = lb.z ? 1 : 0;
        m.w = lb.w ? 1 : 0;
        reinterpret_cast<uchar4*>(out_mask)[idx] = m;
    }
}

extern "C" void kernel_launch(void* const* d_in, const int* in_sizes, int n_in,
                              void* d_out, int out_size)
{
    // metadata order:
    //   0: vessel_labels  int32  [N]
    //   1: parenchyma     f32    [N]
    //   2: vessel_texture f32    [N]
    //   3: intensity_lut  f32    [302]
    const int*   labels = (const int*)  d_in[0];
    const float* par    = (const float*)d_in[1];
    const float* tex    = (const float*)d_in[2];
    const float* lut    = (const float*)d_in[3];

    int n     = in_sizes[0];
    int lut_n = in_sizes[3];
    int n4    = n / 4;

    float* out_vol = (float*)d_out;

    dim3 block(256);
    dim3 grid((n4 + 255) / 256);
    bool exact = (n4 % 256) == 0;

    if (out_size >= 2 * n) {
        void* out_mask = (void*)(out_vol + n);
        if (exact)
            octvol_kernel<true, true><<<grid, block>>>(
                (const int4*)labels, (const float4*)par, (const float4*)tex,
                lut, lut_n, (float4*)out_vol, out_mask, n4);
        else
            octvol_kernel<true, false><<<grid, block>>>(
                (const int4*)labels, (const float4*)par, (const float4*)tex,
                lut, lut_n, (float4*)out_vol, out_mask, n4);
    } else {
        void* out_mask = (void*)((char*)d_out + (size_t)n * sizeof(float));
        if (exact)
            octvol_kernel<false, true><<<grid, block>>>(
                (const int4*)labels, (const float4*)par, (const float4*)tex,
                lut, lut_n, (float4*)out_vol, out_mask, n4);
        else
            octvol_kernel<false, false><<<grid, block>>>(
                (const int4*)labels, (const float4*)par, (const float4*)tex,
                lut, lut_n, (float4*)out_vol, out_mask, n4);
    }
}

// round 9
// speedup vs baseline: 1.0078x; 1.0024x over previous
#include <cuda_runtime.h>
#include <cstdint>

#define LUT_MAX 512   // actual LUT is 302 entries
#define BLOCK   512   // R9: last untested knob (R7 used 256)

// Converged structure: 1 x float4 per thread, flat grid, plain vectorized
// loads/stores, shared-memory LUT, EXACT fast path (n4 % BLOCK == 0).
template <bool MASK_AS_FLOAT, bool EXACT>
__global__ __launch_bounds__(BLOCK)
void octvol_kernel(const int4* __restrict__ labels4,
                   const float4* __restrict__ par4,
                   const float4* __restrict__ tex4,
                   const float* __restrict__ lut,
                   int lut_n,
                   float4* __restrict__ out_vol4,
                   void* __restrict__ out_mask,
                   int n4)
{
    __shared__ float s_lut[LUT_MAX];
    for (int i = threadIdx.x; i < lut_n; i += blockDim.x)
        s_lut[i] = lut[i];
    __syncthreads();

    int idx = blockIdx.x * blockDim.x + threadIdx.x;
    if (!EXACT && idx >= n4) return;

    int4   lb = labels4[idx];
    float4 pa = par4[idx];
    float4 tx = tex4[idx];

    float s0 = s_lut[lb.x];
    float s1 = s_lut[lb.y];
    float s2 = s_lut[lb.z];
    float s3 = s_lut[lb.w];

    float v0 = s0 * tx.x; if (v0 == 0.0f) v0 = 1.0f;
    float v1 = s1 * tx.y; if (v1 == 0.0f) v1 = 1.0f;
    float v2 = s2 * tx.z; if (v2 == 0.0f) v2 = 1.0f;
    float v3 = s3 * tx.w; if (v3 == 0.0f) v3 = 1.0f;

    float4 o;
    o.x = pa.x * v0;
    o.y = pa.y * v1;
    o.z = pa.z * v2;
    o.w = pa.w * v3;
    out_vol4[idx] = o;

    if (MASK_AS_FLOAT) {
        float4 m;
        m.x = lb.x ? 1.0f : 0.0f;
        m.y = lb.y ? 1.0f : 0.0f;
        m.z = lb.z ? 1.0f : 0.0f;
        m.w = lb.w ? 1.0f : 0.0f;
        reinterpret_cast<float4*>(out_mask)[idx] = m;
    } else {
        uchar4 m;
        m.x = lb.x ? 1 : 0;
        m.y = lb.y ? 1 : 0;
        m.z = lb.z ? 1 : 0;
        m.w = lb.w ? 1 : 0;
        reinterpret_cast<uchar4*>(out_mask)[idx] = m;
    }
}

extern "C" void kernel_launch(void* const* d_in, const int* in_sizes, int n_in,
                              void* d_out, int out_size)
{
    // metadata order:
    //   0: vessel_labels  int32  [N]
    //   1: parenchyma     f32    [N]
    //   2: vessel_texture f32    [N]
    //   3: intensity_lut  f32    [302]
    const int*   labels = (const int*)  d_in[0];
    const float* par    = (const float*)d_in[1];
    const float* tex    = (const float*)d_in[2];
    const float* lut    = (const float*)d_in[3];

    int n     = in_sizes[0];
    int lut_n = in_sizes[3];
    int n4    = n / 4;

    float* out_vol = (float*)d_out;

    dim3 block(BLOCK);
    dim3 grid((n4 + BLOCK - 1) / BLOCK);
    bool exact = (n4 % BLOCK) == 0;

    if (out_size >= 2 * n) {
        void* out_mask = (void*)(out_vol + n);
        if (exact)
            octvol_kernel<true, true><<<grid, block>>>(
                (const int4*)labels, (const float4*)par, (const float4*)tex,
                lut, lut_n, (float4*)out_vol, out_mask, n4);
        else
            octvol_kernel<true, false><<<grid, block>>>(
                (const int4*)labels, (const float4*)par, (const float4*)tex,
                lut, lut_n, (float4*)out_vol, out_mask, n4);
    } else {
        void* out_mask = (void*)((char*)d_out + (size_t)n * sizeof(float));
        if (exact)
            octvol_kernel<false, true><<<grid, block>>>(
                (const int4*)labels, (const float4*)par, (const float4*)tex,
                lut, lut_n, (float4*)out_vol, out_mask, n4);
        else
            octvol_kernel<false, false><<<grid, block>>>(
                (const int4*)labels, (const float4*)par, (const float4*)tex,
                lut, lut_n, (float4*)out_vol, out_mask, n4);
    }
}